// round 12
// baseline (speedup 1.0000x reference)
#include <cuda_runtime.h>
#include <cstdint>

#define NQ   4
#define DIM  16
#define NC   4
#define BLK  256
#define WARPS_PER_BLK 8
#define GRID 444                                // 3 blocks/SM x 148 SM, all co-resident
#define WARPS_TOTAL (GRID * WARPS_PER_BLK)      // 3552
#define GROUP_ROWS 32
#define MAX_G 3                                 // ceil(8192 / 3552)

__device__ double g_acc[8];
__device__ float  g_scale[NC];
__device__ float  g_shift[NC];
__device__ unsigned g_cnt;
__device__ int g_flag;

__global__ void k_init() {
    if (threadIdx.x < 8) g_acc[threadIdx.x] = 0.0;
    if (threadIdx.x == 0) { g_cnt = 0u; g_flag = 0; }
}

__global__ void __launch_bounds__(BLK, 3) k_persist(
    const float* __restrict__ x,
    const float* __restrict__ wts,
    const float* __restrict__ W,
    const float* __restrict__ bias,
    const float* __restrict__ gamma,
    const float* __restrict__ beta,
    float* __restrict__ out,
    int B, float invB)
{
    __shared__ float csm[40];          // [0:8)=wc [8:16)=ws [16:32)=W [32:36)=bias
    __shared__ float rsm[8][WARPS_PER_BLK];

    const int t = threadIdx.x;
    const int lane = t & 31;
    const int wid  = t >> 5;
    const int gw   = blockIdx.x * WARPS_PER_BLK + wid;
    const int totalGroups = B / GROUP_ROWS;     // 8192

    if (t < 8) {
        float c, s; __sincosf(wts[t] * 0.5f, &s, &c);
        csm[t] = c; csm[8 + t] = s;
    } else if (t < 24) {
        csm[16 + (t - 8)] = W[t - 8];
    } else if (t < 28) {
        csm[32 + (t - 24)] = bias[t - 24];
    }
    __syncthreads();

    // per-lane static info for the segment loads
    const int base = lane & 7;                  // float4 slot within 8-lane stride
    const int sub  = lane >> 3;                 // which of 4 samples in segment
    // contribution class per m (j = base + 8m): pos = j%3, top = j<18
    // pos==0 -> L+=all4 ; pos==1 -> L+=xy, R+=zw ; pos==2 -> R+=all4

    float lg[MAX_G][4];
    float sum0=0.f,sum1=0.f,sum2=0.f,sum3=0.f, sq0=0.f,sq1=0.f,sq2=0.f,sq3=0.f;

    #pragma unroll 1
    for (int kg = 0; kg < MAX_G; kg++) {
        int g = gw + kg * WARPS_TOTAL;
        if (g >= totalGroups) break;

        // this thread will end up owning sample (g*32 + lane)
        float TLo = 0.f, TRo = 0.f, BLo = 0.f, BRo = 0.f;

        const float4* gsrc = (const float4*)(x + (size_t)g * GROUP_ROWS * 144);

        #pragma unroll
        for (int seg = 0; seg < 8; seg++) {
            const float4* sp = gsrc + seg * 144 + sub * 36 + base;
            // 5 loads: m=0..3 always, m=4 only meaningful for base<4 (dummy-safe addr)
            float4 v0 = __ldcs(sp);
            float4 v1 = __ldcs(sp + 8);
            float4 v2 = __ldcs(sp + 16);
            float4 v3 = __ldcs(sp + 24);
            float4 v4 = __ldcs(sp + ((base < 4) ? 32 : 0));

            float TL = 0.f, TR = 0.f, BL = 0.f, BR = 0.f;
            #pragma unroll
            for (int m = 0; m < 5; m++) {
                float4 v = (m == 0) ? v0 : (m == 1) ? v1 : (m == 2) ? v2 : (m == 3) ? v3 : v4;
                int j = base + 8 * m;           // 0..39
                bool valid = (m < 4) | (base < 4);
                int pos = j % 3;
                bool top = j < 18;
                float sa = v.x + v.y;
                float sb = v.z + v.w;
                float s4 = sa + sb;
                float La = (pos == 0) ? s4 : ((pos == 1) ? sa : 0.f);
                float Ra = (pos == 2) ? s4 : ((pos == 1) ? sb : 0.f);
                if (!valid) { La = 0.f; Ra = 0.f; }
                if (top) { TL += La; TR += Ra; }
                else     { BL += La; BR += Ra; }
            }
            // reduce over the 8 lanes sharing this sample
            #pragma unroll
            for (int d = 1; d < 8; d <<= 1) {
                TL += __shfl_xor_sync(0xFFFFFFFFu, TL, d);
                TR += __shfl_xor_sync(0xFFFFFFFFu, TR, d);
                BL += __shfl_xor_sync(0xFFFFFFFFu, BL, d);
                BR += __shfl_xor_sync(0xFFFFFFFFu, BR, d);
            }
            // route: sample (4*seg + q) lives in lane-group q; lane l wants sample l
            int src = 8 * (lane & 3);
            float gTL = __shfl_sync(0xFFFFFFFFu, TL, src);
            float gTR = __shfl_sync(0xFFFFFFFFu, TR, src);
            float gBL = __shfl_sync(0xFFFFFFFFu, BL, src);
            float gBR = __shfl_sync(0xFFFFFFFFu, BR, src);
            if ((lane >> 2) == seg) { TLo = gTL; TRo = gTR; BLo = gBL; BRo = gBR; }
        }

        // ---- circuit (fused RX+RY1 product state; final CZ dropped) ----
        const float inv72 = 1.f / 72.f;         // (1/36) * 0.5
        float cp4[4], sp4[4];
        __sincosf(TLo * inv72, &sp4[0], &cp4[0]);
        __sincosf(TRo * inv72, &sp4[1], &cp4[1]);
        __sincosf(BLo * inv72, &sp4[2], &cp4[2]);
        __sincosf(BRo * inv72, &sp4[3], &cp4[3]);

        float v0r[4], v0i[4], v1r[4], v1i[4];
        #pragma unroll
        for (int i = 0; i < 4; i++) {
            float cw = csm[i], sw = csm[8 + i];
            v0r[i] =  cw * cp4[i];  v0i[i] =  sw * sp4[i];
            v1r[i] =  sw * cp4[i];  v1i[i] = -cw * sp4[i];
        }
        float p01r[4], p01i[4], p23r[4], p23i[4];
        #pragma unroll
        for (int a = 0; a < 2; a++) {
            float ar0 = a ? v1r[0] : v0r[0], ai0 = a ? v1i[0] : v0i[0];
            float ar2 = a ? v1r[2] : v0r[2], ai2 = a ? v1i[2] : v0i[2];
            #pragma unroll
            for (int c = 0; c < 2; c++) {
                float br1 = c ? v1r[1] : v0r[1], bi1 = c ? v1i[1] : v0i[1];
                float br3 = c ? v1r[3] : v0r[3], bi3 = c ? v1i[3] : v0i[3];
                p01r[a*2+c] = ar0 * br1 - ai0 * bi1;
                p01i[a*2+c] = ar0 * bi1 + ai0 * br1;
                p23r[a*2+c] = ar2 * br3 - ai2 * bi3;
                p23i[a*2+c] = ar2 * bi3 + ai2 * br3;
            }
        }
        float re[DIM], im[DIM];
        #pragma unroll
        for (int k = 0; k < DIM; k++) {
            int a = (k >> 2) & 3, c = k & 3;
            float rr = p01r[a] * p23r[c] - p01i[a] * p23i[c];
            float ii = p01r[a] * p23i[c] + p01i[a] * p23r[c];
            int par = (((k >> 3) & (k >> 2)) ^ ((k >> 2) & (k >> 1)) ^ ((k >> 1) & k)) & 1;
            re[k] = par ? -rr : rr;
            im[k] = par ? -ii : ii;
        }
        #pragma unroll
        for (int w = 0; w < NQ; w++) {
            float cc = csm[4 + w], ss = csm[12 + w];
            int bit = 1 << (3 - w);
            #pragma unroll
            for (int k = 0; k < DIM; k++) {
                if (!(k & bit)) {
                    int k1 = k | bit;
                    float r0 = re[k], r1 = re[k1];
                    re[k]  = cc * r0 - ss * r1;
                    re[k1] = ss * r0 + cc * r1;
                    float i0 = im[k], i1 = im[k1];
                    im[k]  = cc * i0 - ss * i1;
                    im[k1] = ss * i0 + cc * i1;
                }
            }
        }
        float q0=0.f, q1=0.f, q2=0.f, q3=0.f;
        #pragma unroll
        for (int k = 0; k < DIM; k++) {
            float p = re[k] * re[k] + im[k] * im[k];
            q0 += (k & 8) ? -p : p;
            q1 += (k & 4) ? -p : p;
            q2 += (k & 2) ? -p : p;
            q3 += (k & 1) ? -p : p;
        }
        float l0 = csm[32] + q0*csm[16+0] + q1*csm[16+1] + q2*csm[16+2]  + q3*csm[16+3];
        float l1 = csm[33] + q0*csm[16+4] + q1*csm[16+5] + q2*csm[16+6]  + q3*csm[16+7];
        float l2 = csm[34] + q0*csm[16+8] + q1*csm[16+9] + q2*csm[16+10] + q3*csm[16+11];
        float l3 = csm[35] + q0*csm[16+12]+ q1*csm[16+13]+ q2*csm[16+14] + q3*csm[16+15];

        lg[kg][0] = l0; lg[kg][1] = l1; lg[kg][2] = l2; lg[kg][3] = l3;
        sum0 += l0; sum1 += l1; sum2 += l2; sum3 += l3;
        sq0 += l0*l0; sq1 += l1*l1; sq2 += l2*l2; sq3 += l3*l3;
    }

    // ---- block reduction ----
    float red[8] = {sum0,sum1,sum2,sum3,sq0,sq1,sq2,sq3};
    #pragma unroll
    for (int off = 16; off > 0; off >>= 1) {
        #pragma unroll
        for (int j = 0; j < 8; j++)
            red[j] += __shfl_down_sync(0xFFFFFFFFu, red[j], off);
    }
    if (lane == 0) {
        #pragma unroll
        for (int j = 0; j < 8; j++) rsm[j][wid] = red[j];
    }
    __syncthreads();
    if (t < 8) {
        float acc = 0.f;
        #pragma unroll
        for (int wgi = 0; wgi < WARPS_PER_BLK; wgi++) acc += rsm[t][wgi];
        atomicAdd(&g_acc[t], (double)acc);
        __threadfence();
    }
    __syncthreads();

    // ---- grid barrier (444 blocks, 3/SM, all co-resident) ----
    if (t == 0) {
        unsigned r = atomicAdd(&g_cnt, 1u);
        if (r == gridDim.x - 1u) {
            #pragma unroll
            for (int c2 = 0; c2 < NC; c2++) {
                double m = g_acc[c2] * (double)invB;
                double v = g_acc[4 + c2] * (double)invB - m * m;
                float inv = rsqrtf((float)v + 1e-5f);
                g_scale[c2] = gamma[c2] * inv;
                g_shift[c2] = beta[c2] - (float)m * inv * gamma[c2];
            }
            __threadfence();
            atomicExch(&g_flag, 1);
        } else {
            while (atomicAdd(&g_flag, 0) == 0) __nanosleep(64);
        }
    }
    __syncthreads();

    float sc[4], sh[4];
    #pragma unroll
    for (int c2 = 0; c2 < NC; c2++) {
        sc[c2] = *((volatile float*)&g_scale[c2]);
        sh[c2] = *((volatile float*)&g_shift[c2]);
    }

    // ---- coalesced normalized write (warp writes 32 consecutive float4) ----
    float4* o4 = (float4*)out;
    #pragma unroll
    for (int kg = 0; kg < MAX_G; kg++) {
        int g = gw + kg * WARPS_TOTAL;
        if (g < totalGroups) {
            o4[(size_t)g * GROUP_ROWS + lane] =
                make_float4(lg[kg][0]*sc[0]+sh[0], lg[kg][1]*sc[1]+sh[1],
                            lg[kg][2]*sc[2]+sh[2], lg[kg][3]*sc[3]+sh[3]);
        }
    }
}

extern "C" void kernel_launch(void* const* d_in, const int* in_sizes, int n_in,
                              void* d_out, int out_size) {
    const float* x     = (const float*)d_in[0];
    const float* wts   = (const float*)d_in[1];
    const float* W     = (const float*)d_in[2];
    const float* bias  = (const float*)d_in[3];
    const float* gamma = (const float*)d_in[4];
    const float* beta  = (const float*)d_in[5];
    float* out = (float*)d_out;

    int B = in_sizes[0] / 144;    // 262144

    k_init<<<1, 32>>>();
    k_persist<<<GRID, BLK>>>(x, wts, W, bias, gamma, beta, out, B, 1.0f / (float)B);
}

// round 13
// speedup vs baseline: 1.3824x; 1.3824x over previous
#include <cuda_runtime.h>
#include <cstdint>

#define NQ   4
#define DIM  16
#define NC   4
#define BLK  256
#define GRID 444                        // 3 blocks/SM x 148 SMs, all co-resident
#define MAX_IT 3                        // ceil(1024 units / 444)
#define CHUNK_ROWS 32
#define ROW_PITCH 592                   // bytes per sample-row; conflict-free LDS.128
#define CHUNK_BYTES (CHUNK_ROWS * ROW_PITCH)    // 18944
#define PART_PITCH 9

// smem layout (bytes)
#define OFF_BUF0  0
#define OFF_BUF1  CHUNK_BYTES                           // 18944
#define OFF_PART  (2 * CHUNK_BYTES)                     // 37888 (256*9*4 = 9216)
#define OFF_LSM   (OFF_PART + 256 * PART_PITCH * 4)     // 47104 (3*256*16 = 12288)
#define OFF_CONST (OFF_LSM + MAX_IT * 256 * 16)         // 59392 (40 floats)
#define SMEM_BYTES (OFF_CONST + 40 * 4)                 // 59552

__device__ double g_acc[8];
__device__ float  g_scale[NC];
__device__ float  g_shift[NC];
__device__ unsigned g_cnt;
__device__ int g_flag;

__global__ void k_init() {
    if (threadIdx.x < 8) g_acc[threadIdx.x] = 0.0;
    if (threadIdx.x == 0) { g_cnt = 0u; g_flag = 0; }
}

__device__ __forceinline__ void cp16(char* dst_smem, const float4* src) {
    unsigned d = (unsigned)__cvta_generic_to_shared(dst_smem);
    asm volatile("cp.async.cg.shared.global [%0], [%1], 16;\n" :: "r"(d), "l"(src));
}
__device__ __forceinline__ void cp_commit() { asm volatile("cp.async.commit_group;\n"); }
template<int N> __device__ __forceinline__ void cp_wait() {
    asm volatile("cp.async.wait_group %0;\n" :: "n"(N));
}

__global__ void __launch_bounds__(BLK, 3) k_persist(
    const float* __restrict__ x,
    const float* __restrict__ wts,
    const float* __restrict__ W,
    const float* __restrict__ bias,
    const float* __restrict__ gamma,
    const float* __restrict__ beta,
    float* __restrict__ out,
    int units, float invB)              // units = B/256
{
    extern __shared__ char smem[];
    char*  bufs[2] = { smem + OFF_BUF0, smem + OFF_BUF1 };
    float* part = (float*)(smem + OFF_PART);
    float* lsm  = (float*)(smem + OFF_LSM);
    float* csm  = (float*)(smem + OFF_CONST);   // [0:8)=wc [8:16)=ws [16:32)=W [32:36)=bias

    const int t = threadIdx.x;
    const int b = blockIdx.x;

    if (t < 8) {
        float c, s; __sincosf(wts[t] * 0.5f, &s, &c);
        csm[t] = c; csm[8 + t] = s;
    } else if (t < 24) {
        csm[16 + (t - 8)] = W[t - 8];
    } else if (t < 28) {
        csm[32 + (t - 24)] = bias[t - 24];
    }

    // cp.async dst offsets: only threads t<128 load; idx = t + 128k, k=0..8
    unsigned coff[9];
    #pragma unroll
    for (int k = 0; k < 9; k++) {
        int idx = t + 128 * k;
        int row = idx / 36, col = idx % 36;
        coff[k] = (unsigned)row * ROW_PITCH + (unsigned)col * 16u;
    }
    __syncthreads();

    // issue one 32-row chunk (1152 float4, 9 per thread for t<128), coalesced
    auto issue32 = [&](char* dst, size_t row0) {
        const float4* src = (const float4*)(x + row0 * 144);
        #pragma unroll
        for (int k = 0; k < 9; k++) cp16(dst + coff[k], src + (t + 128 * k));
        cp_commit();
    };
    // pool one chunk (t<128): thread -> (row r=t&31, quarter q=t>>5)
    auto pool32 = [&](const char* buf, int c) {
        int r = t & 31, q = t >> 5;
        const char* rb = buf + (unsigned)r * ROW_PITCH + (unsigned)q * 144u;
        float L = 0.f, R = 0.f;
        #pragma unroll
        for (int j = 0; j < 9; j++) {
            float4 v = *(const float4*)(rb + 16 * j);
            int pos = j % 3;
            if (pos == 0)      { L += v.x + v.y + v.z + v.w; }
            else if (pos == 1) { L += v.x + v.y; R += v.z + v.w; }
            else               { R += v.x + v.y + v.z + v.w; }
        }
        float* p = part + (unsigned)(c * 32 + r) * PART_PITCH + 2u * q;
        p[0] = L; p[1] = R;
    };

    float sum0=0.f,sum1=0.f,sum2=0.f,sum3=0.f, sq0=0.f,sq1=0.f,sq2=0.f,sq3=0.f;

    // prologue: chunks 0,1 of first unit
    if (t < 128) {
        size_t r0 = (size_t)b * 256;
        issue32(bufs[0], r0);
        issue32(bufs[1], r0 + CHUNK_ROWS);
    }

    #pragma unroll 1
    for (int it = 0; it < MAX_IT; it++) {
        int u = b + it * GRID;
        if (u >= units) break;
        size_t ub = (size_t)u * 256;
        int un = u + GRID;
        bool nv = un < units;
        size_t nb = (size_t)un * 256;

        #pragma unroll 1
        for (int c = 0; c < 8; c++) {
            if (t < 128) {
                if (c == 7 && !nv) cp_wait<0>(); else cp_wait<1>();
            }
            __syncthreads();
            if (t < 128) pool32(bufs[c & 1], c);
            __syncthreads();
            if (t < 128) {
                if (c < 6)      issue32(bufs[c & 1], ub + (size_t)(c + 2) * CHUNK_ROWS);
                else if (nv)    issue32(bufs[c & 1], nb + (size_t)(c - 6) * CHUNK_ROWS);
            }
        }

        // ---- per-thread sample circuit (fused RX+RY1; final CZ dropped) ----
        const float* pp = part + (unsigned)t * PART_PITCH;
        float TL = pp[0] + pp[2], TR = pp[1] + pp[3];
        float BL = pp[4] + pp[6], BR = pp[5] + pp[7];

        const float inv72 = 1.f / 72.f;   // (1/36)*0.5
        float cp4[4], sp4[4];
        __sincosf(TL * inv72, &sp4[0], &cp4[0]);
        __sincosf(TR * inv72, &sp4[1], &cp4[1]);
        __sincosf(BL * inv72, &sp4[2], &cp4[2]);
        __sincosf(BR * inv72, &sp4[3], &cp4[3]);

        float v0r[4], v0i[4], v1r[4], v1i[4];
        #pragma unroll
        for (int i = 0; i < 4; i++) {
            float cw = csm[i], sw = csm[8 + i];
            v0r[i] =  cw * cp4[i];  v0i[i] =  sw * sp4[i];
            v1r[i] =  sw * cp4[i];  v1i[i] = -cw * sp4[i];
        }
        float p01r[4], p01i[4], p23r[4], p23i[4];
        #pragma unroll
        for (int a = 0; a < 2; a++) {
            float ar0 = a ? v1r[0] : v0r[0], ai0 = a ? v1i[0] : v0i[0];
            float ar2 = a ? v1r[2] : v0r[2], ai2 = a ? v1i[2] : v0i[2];
            #pragma unroll
            for (int c = 0; c < 2; c++) {
                float br1 = c ? v1r[1] : v0r[1], bi1 = c ? v1i[1] : v0i[1];
                float br3 = c ? v1r[3] : v0r[3], bi3 = c ? v1i[3] : v0i[3];
                p01r[a*2+c] = ar0 * br1 - ai0 * bi1;
                p01i[a*2+c] = ar0 * bi1 + ai0 * br1;
                p23r[a*2+c] = ar2 * br3 - ai2 * bi3;
                p23i[a*2+c] = ar2 * bi3 + ai2 * br3;
            }
        }
        float re[DIM], im[DIM];
        #pragma unroll
        for (int k = 0; k < DIM; k++) {
            int a = (k >> 2) & 3, c = k & 3;
            float rr = p01r[a] * p23r[c] - p01i[a] * p23i[c];
            float ii = p01r[a] * p23i[c] + p01i[a] * p23r[c];
            int par = (((k >> 3) & (k >> 2)) ^ ((k >> 2) & (k >> 1)) ^ ((k >> 1) & k)) & 1;
            re[k] = par ? -rr : rr;
            im[k] = par ? -ii : ii;
        }
        #pragma unroll
        for (int w = 0; w < NQ; w++) {
            float cc = csm[4 + w], ss = csm[12 + w];
            int bit = 1 << (3 - w);
            #pragma unroll
            for (int k = 0; k < DIM; k++) {
                if (!(k & bit)) {
                    int k1 = k | bit;
                    float r0 = re[k], r1 = re[k1];
                    re[k]  = cc * r0 - ss * r1;
                    re[k1] = ss * r0 + cc * r1;
                    float i0 = im[k], i1 = im[k1];
                    im[k]  = cc * i0 - ss * i1;
                    im[k1] = ss * i0 + cc * i1;
                }
            }
        }
        float q0=0.f, q1=0.f, q2=0.f, q3=0.f;
        #pragma unroll
        for (int k = 0; k < DIM; k++) {
            float p = re[k] * re[k] + im[k] * im[k];
            q0 += (k & 8) ? -p : p;
            q1 += (k & 4) ? -p : p;
            q2 += (k & 2) ? -p : p;
            q3 += (k & 1) ? -p : p;
        }
        float l0 = csm[32] + q0*csm[16+0] + q1*csm[16+1] + q2*csm[16+2]  + q3*csm[16+3];
        float l1 = csm[33] + q0*csm[16+4] + q1*csm[16+5] + q2*csm[16+6]  + q3*csm[16+7];
        float l2 = csm[34] + q0*csm[16+8] + q1*csm[16+9] + q2*csm[16+10] + q3*csm[16+11];
        float l3 = csm[35] + q0*csm[16+12]+ q1*csm[16+13]+ q2*csm[16+14] + q3*csm[16+15];

        *(float4*)(lsm + (unsigned)(it * 256 + t) * 4u) = make_float4(l0, l1, l2, l3);
        sum0 += l0; sum1 += l1; sum2 += l2; sum3 += l3;
        sq0 += l0*l0; sq1 += l1*l1; sq2 += l2*l2; sq3 += l3*l3;
    }

    // ---- block reduction ----
    float red[8] = {sum0,sum1,sum2,sum3,sq0,sq1,sq2,sq3};
    #pragma unroll
    for (int off = 16; off > 0; off >>= 1) {
        #pragma unroll
        for (int j = 0; j < 8; j++)
            red[j] += __shfl_down_sync(0xFFFFFFFFu, red[j], off);
    }
    __syncthreads();
    float* rsm = part;   // reuse partial area (done with it)
    int lane = t & 31, wid = t >> 5;
    if (lane == 0) {
        #pragma unroll
        for (int j = 0; j < 8; j++) rsm[j * 8 + wid] = red[j];
    }
    __syncthreads();
    if (t < 8) {
        float acc = 0.f;
        #pragma unroll
        for (int wgi = 0; wgi < 8; wgi++) acc += rsm[t * 8 + wgi];
        atomicAdd(&g_acc[t], (double)acc);
        __threadfence();
    }
    __syncthreads();

    // ---- grid barrier (444 blocks, 3/SM, all co-resident) ----
    if (t == 0) {
        unsigned r = atomicAdd(&g_cnt, 1u);
        if (r == gridDim.x - 1u) {
            #pragma unroll
            for (int c2 = 0; c2 < NC; c2++) {
                double m = g_acc[c2] * (double)invB;
                double v = g_acc[4 + c2] * (double)invB - m * m;
                float inv = rsqrtf((float)v + 1e-5f);
                g_scale[c2] = gamma[c2] * inv;
                g_shift[c2] = beta[c2] - (float)m * inv * gamma[c2];
            }
            __threadfence();
            atomicExch(&g_flag, 1);
        } else {
            while (atomicAdd(&g_flag, 0) == 0) __nanosleep(64);
        }
    }
    __syncthreads();

    float sc[4], sh[4];
    #pragma unroll
    for (int c2 = 0; c2 < NC; c2++) {
        sc[c2] = *((volatile float*)&g_scale[c2]);
        sh[c2] = *((volatile float*)&g_shift[c2]);
    }

    // ---- coalesced normalized write from smem-held logits ----
    float4* o4 = (float4*)out;
    #pragma unroll 1
    for (int it = 0; it < MAX_IT; it++) {
        int u = b + it * GRID;
        if (u >= units) break;
        float4 l = *(const float4*)(lsm + (unsigned)(it * 256 + t) * 4u);
        o4[(size_t)u * 256 + t] =
            make_float4(l.x*sc[0]+sh[0], l.y*sc[1]+sh[1], l.z*sc[2]+sh[2], l.w*sc[3]+sh[3]);
    }
}

extern "C" void kernel_launch(void* const* d_in, const int* in_sizes, int n_in,
                              void* d_out, int out_size) {
    const float* x     = (const float*)d_in[0];
    const float* wts   = (const float*)d_in[1];
    const float* W     = (const float*)d_in[2];
    const float* bias  = (const float*)d_in[3];
    const float* gamma = (const float*)d_in[4];
    const float* beta  = (const float*)d_in[5];
    float* out = (float*)d_out;

    int B = in_sizes[0] / 144;          // 262144
    int units = B / 256;                // 1024

    cudaFuncSetAttribute(k_persist, cudaFuncAttributeMaxDynamicSharedMemorySize, SMEM_BYTES);

    k_init<<<1, 32>>>();
    k_persist<<<GRID, BLK, SMEM_BYTES>>>(x, wts, W, bias, gamma, beta, out,
                                         units, 1.0f / (float)B);
}

// round 14
// speedup vs baseline: 1.4242x; 1.0303x over previous
#include <cuda_runtime.h>
#include <cstdint>

#define NQ   4
#define DIM  16
#define NC   4
#define BLK  256
#define GRID 296                        // 2 blocks/SM x 148 SMs, all co-resident
#define MAX_IT 4                        // ceil(1024 units / 296)
#define CHUNK_ROWS 32
#define ROW_PITCH 592                   // bytes/sample-row; conflict-free LDS.128
#define CHUNK_BYTES (CHUNK_ROWS * ROW_PITCH)    // 18944
#define NBUF 4
#define PART_PITCH 9

// smem layout (bytes)
#define OFF_BUF   0                                     // 4 * 18944 = 75776
#define OFF_PART  (NBUF * CHUNK_BYTES)                  // 75776 (256*9*4 = 9216)
#define OFF_LSM   (OFF_PART + 256 * PART_PITCH * 4)     // 84992 (4*256*16 = 16384)
#define OFF_CONST (OFF_LSM + MAX_IT * 256 * 16)         // 101376 (40 floats)
#define SMEM_BYTES (OFF_CONST + 40 * 4)                 // 101536

__device__ double g_acc[8];
__device__ float  g_scale[NC];
__device__ float  g_shift[NC];
__device__ unsigned g_cnt;
__device__ int g_flag;

__global__ void k_init() {
    if (threadIdx.x < 8) g_acc[threadIdx.x] = 0.0;
    if (threadIdx.x == 0) { g_cnt = 0u; g_flag = 0; }
}

__device__ __forceinline__ void cp16(char* dst_smem, const float4* src) {
    unsigned d = (unsigned)__cvta_generic_to_shared(dst_smem);
    asm volatile("cp.async.cg.shared.global [%0], [%1], 16;\n" :: "r"(d), "l"(src));
}
__device__ __forceinline__ void cp_commit() { asm volatile("cp.async.commit_group;\n"); }
template<int N> __device__ __forceinline__ void cp_wait() {
    asm volatile("cp.async.wait_group %0;\n" :: "n"(N));
}

__global__ void __launch_bounds__(BLK, 2) k_persist(
    const float* __restrict__ x,
    const float* __restrict__ wts,
    const float* __restrict__ W,
    const float* __restrict__ bias,
    const float* __restrict__ gamma,
    const float* __restrict__ beta,
    float* __restrict__ out,
    int units, float invB)              // units = B/256
{
    extern __shared__ char smem[];
    float* part = (float*)(smem + OFF_PART);
    float* lsm  = (float*)(smem + OFF_LSM);
    float* csm  = (float*)(smem + OFF_CONST);   // [0:8)=wc [8:16)=ws [16:32)=W [32:36)=bias

    const int t = threadIdx.x;
    const int b = blockIdx.x;

    if (t < 8) {
        float c, s; __sincosf(wts[t] * 0.5f, &s, &c);
        csm[t] = c; csm[8 + t] = s;
    } else if (t < 24) {
        csm[16 + (t - 8)] = W[t - 8];
    } else if (t < 28) {
        csm[32 + (t - 24)] = bias[t - 24];
    }

    // 32-row chunk = 1152 float4 = 4.5 per thread: k=0..3 all threads, k=4 for t<128
    unsigned coff[5];
    #pragma unroll
    for (int k = 0; k < 5; k++) {
        int idx = (k < 4) ? (t + 256 * k) : (1024 + t);
        int row = idx / 36, col = idx % 36;
        coff[k] = (unsigned)row * ROW_PITCH + (unsigned)col * 16u;
    }
    const bool has5 = (t < 128);
    __syncthreads();

    // issue one 32-row chunk into buffer bi (coalesced, one commit group)
    auto issue32 = [&](int bi, size_t row0) {
        char* dst = smem + bi * CHUNK_BYTES;
        const float4* src = (const float4*)(x + row0 * 144);
        cp16(dst + coff[0], src + t);
        cp16(dst + coff[1], src + t + 256);
        cp16(dst + coff[2], src + t + 512);
        cp16(dst + coff[3], src + t + 768);
        if (has5) cp16(dst + coff[4], src + 1024 + t);
        cp_commit();
    };
    // pool a 64-row pair living in buffers b0 (rows 0-31) and b1 (rows 32-63)
    auto pool_pair = [&](int b0, int b1, int p) {
        int r = t & 63, q = t >> 6;
        const char* buf = smem + ((r < 32) ? b0 : b1) * CHUNK_BYTES;
        const char* rb = buf + (unsigned)(r & 31) * ROW_PITCH + (unsigned)q * 144u;
        float L = 0.f, R = 0.f;
        #pragma unroll
        for (int j = 0; j < 9; j++) {
            float4 v = *(const float4*)(rb + 16 * j);
            int pos = j % 3;
            if (pos == 0)      { L += v.x + v.y + v.z + v.w; }
            else if (pos == 1) { L += v.x + v.y; R += v.z + v.w; }
            else               { R += v.x + v.y + v.z + v.w; }
        }
        float* pd = part + (unsigned)(p * 64 + r) * PART_PITCH + 2u * q;
        pd[0] = L; pd[1] = R;
    };

    float sum0=0.f,sum1=0.f,sum2=0.f,sum3=0.f, sq0=0.f,sq1=0.f,sq2=0.f,sq3=0.f;

    // prologue: chunks 0..3 of first unit into buffers 0..3 (4 commit groups)
    {
        size_t r0 = (size_t)b * 256;
        issue32(0, r0);
        issue32(1, r0 + CHUNK_ROWS);
        issue32(2, r0 + 2 * CHUNK_ROWS);
        issue32(3, r0 + 3 * CHUNK_ROWS);
    }

    #pragma unroll 1
    for (int it = 0; it < MAX_IT; it++) {
        int u = b + it * GRID;
        if (u >= units) break;
        size_t ub = (size_t)u * 256;
        bool nv = (u + GRID) < units;
        size_t nb = (size_t)(u + GRID) * 256;

        #pragma unroll
        for (int p = 0; p < 4; p++) {
            int b0 = (2 * p) & 3, b1 = (2 * p + 1) & 3;
            if (p == 3 && !nv) cp_wait<0>(); else cp_wait<2>();
            __syncthreads();
            pool_pair(b0, b1, p);
            __syncthreads();
            if (p < 2) {
                // within-unit chunks c = 2p+4, 2p+5
                issue32(b0, ub + (size_t)(2 * p + 4) * CHUNK_ROWS);
                issue32(b1, ub + (size_t)(2 * p + 5) * CHUNK_ROWS);
            } else if (nv) {
                // next unit's chunks c = 2p-4, 2p-3
                issue32(b0, nb + (size_t)(2 * p - 4) * CHUNK_ROWS);
                issue32(b1, nb + (size_t)(2 * p - 3) * CHUNK_ROWS);
            }
        }

        // ---- per-thread sample circuit (fused RX+RY1; final CZ dropped) ----
        const float* pp = part + (unsigned)t * PART_PITCH;
        float TL = pp[0] + pp[2], TR = pp[1] + pp[3];
        float BL = pp[4] + pp[6], BR = pp[5] + pp[7];

        const float inv72 = 1.f / 72.f;   // (1/36)*0.5
        float cp4[4], sp4[4];
        __sincosf(TL * inv72, &sp4[0], &cp4[0]);
        __sincosf(TR * inv72, &sp4[1], &cp4[1]);
        __sincosf(BL * inv72, &sp4[2], &cp4[2]);
        __sincosf(BR * inv72, &sp4[3], &cp4[3]);

        float v0r[4], v0i[4], v1r[4], v1i[4];
        #pragma unroll
        for (int i = 0; i < 4; i++) {
            float cw = csm[i], sw = csm[8 + i];
            v0r[i] =  cw * cp4[i];  v0i[i] =  sw * sp4[i];
            v1r[i] =  sw * cp4[i];  v1i[i] = -cw * sp4[i];
        }
        float p01r[4], p01i[4], p23r[4], p23i[4];
        #pragma unroll
        for (int a = 0; a < 2; a++) {
            float ar0 = a ? v1r[0] : v0r[0], ai0 = a ? v1i[0] : v0i[0];
            float ar2 = a ? v1r[2] : v0r[2], ai2 = a ? v1i[2] : v0i[2];
            #pragma unroll
            for (int c = 0; c < 2; c++) {
                float br1 = c ? v1r[1] : v0r[1], bi1 = c ? v1i[1] : v0i[1];
                float br3 = c ? v1r[3] : v0r[3], bi3 = c ? v1i[3] : v0i[3];
                p01r[a*2+c] = ar0 * br1 - ai0 * bi1;
                p01i[a*2+c] = ar0 * bi1 + ai0 * br1;
                p23r[a*2+c] = ar2 * br3 - ai2 * bi3;
                p23i[a*2+c] = ar2 * bi3 + ai2 * br3;
            }
        }
        float re[DIM], im[DIM];
        #pragma unroll
        for (int k = 0; k < DIM; k++) {
            int a = (k >> 2) & 3, c = k & 3;
            float rr = p01r[a] * p23r[c] - p01i[a] * p23i[c];
            float ii = p01r[a] * p23i[c] + p01i[a] * p23r[c];
            int par = (((k >> 3) & (k >> 2)) ^ ((k >> 2) & (k >> 1)) ^ ((k >> 1) & k)) & 1;
            re[k] = par ? -rr : rr;
            im[k] = par ? -ii : ii;
        }
        #pragma unroll
        for (int w = 0; w < NQ; w++) {
            float cc = csm[4 + w], ss = csm[12 + w];
            int bit = 1 << (3 - w);
            #pragma unroll
            for (int k = 0; k < DIM; k++) {
                if (!(k & bit)) {
                    int k1 = k | bit;
                    float r0 = re[k], r1 = re[k1];
                    re[k]  = cc * r0 - ss * r1;
                    re[k1] = ss * r0 + cc * r1;
                    float i0 = im[k], i1 = im[k1];
                    im[k]  = cc * i0 - ss * i1;
                    im[k1] = ss * i0 + cc * i1;
                }
            }
        }
        float q0=0.f, q1=0.f, q2=0.f, q3=0.f;
        #pragma unroll
        for (int k = 0; k < DIM; k++) {
            float p = re[k] * re[k] + im[k] * im[k];
            q0 += (k & 8) ? -p : p;
            q1 += (k & 4) ? -p : p;
            q2 += (k & 2) ? -p : p;
            q3 += (k & 1) ? -p : p;
        }
        float l0 = csm[32] + q0*csm[16+0] + q1*csm[16+1] + q2*csm[16+2]  + q3*csm[16+3];
        float l1 = csm[33] + q0*csm[16+4] + q1*csm[16+5] + q2*csm[16+6]  + q3*csm[16+7];
        float l2 = csm[34] + q0*csm[16+8] + q1*csm[16+9] + q2*csm[16+10] + q3*csm[16+11];
        float l3 = csm[35] + q0*csm[16+12]+ q1*csm[16+13]+ q2*csm[16+14] + q3*csm[16+15];

        *(float4*)(lsm + (unsigned)(it * 256 + t) * 4u) = make_float4(l0, l1, l2, l3);
        sum0 += l0; sum1 += l1; sum2 += l2; sum3 += l3;
        sq0 += l0*l0; sq1 += l1*l1; sq2 += l2*l2; sq3 += l3*l3;
    }

    // ---- block reduction ----
    float red[8] = {sum0,sum1,sum2,sum3,sq0,sq1,sq2,sq3};
    #pragma unroll
    for (int off = 16; off > 0; off >>= 1) {
        #pragma unroll
        for (int j = 0; j < 8; j++)
            red[j] += __shfl_down_sync(0xFFFFFFFFu, red[j], off);
    }
    __syncthreads();
    float* rsm = part;   // reuse partial area
    int lane = t & 31, wid = t >> 5;
    if (lane == 0) {
        #pragma unroll
        for (int j = 0; j < 8; j++) rsm[j * 8 + wid] = red[j];
    }
    __syncthreads();
    if (t < 8) {
        float acc = 0.f;
        #pragma unroll
        for (int wgi = 0; wgi < 8; wgi++) acc += rsm[t * 8 + wgi];
        atomicAdd(&g_acc[t], (double)acc);
        __threadfence();
    }
    __syncthreads();

    // ---- grid barrier (296 blocks, 2/SM, all co-resident) ----
    if (t == 0) {
        unsigned r = atomicAdd(&g_cnt, 1u);
        if (r == gridDim.x - 1u) {
            #pragma unroll
            for (int c2 = 0; c2 < NC; c2++) {
                double m = g_acc[c2] * (double)invB;
                double v = g_acc[4 + c2] * (double)invB - m * m;
                float inv = rsqrtf((float)v + 1e-5f);
                g_scale[c2] = gamma[c2] * inv;
                g_shift[c2] = beta[c2] - (float)m * inv * gamma[c2];
            }
            __threadfence();
            atomicExch(&g_flag, 1);
        } else {
            while (atomicAdd(&g_flag, 0) == 0) __nanosleep(64);
        }
    }
    __syncthreads();

    float sc[4], sh[4];
    #pragma unroll
    for (int c2 = 0; c2 < NC; c2++) {
        sc[c2] = *((volatile float*)&g_scale[c2]);
        sh[c2] = *((volatile float*)&g_shift[c2]);
    }

    // ---- coalesced normalized write from smem-held logits ----
    float4* o4 = (float4*)out;
    #pragma unroll 1
    for (int it = 0; it < MAX_IT; it++) {
        int u = b + it * GRID;
        if (u >= units) break;
        float4 l = *(const float4*)(lsm + (unsigned)(it * 256 + t) * 4u);
        o4[(size_t)u * 256 + t] =
            make_float4(l.x*sc[0]+sh[0], l.y*sc[1]+sh[1], l.z*sc[2]+sh[2], l.w*sc[3]+sh[3]);
    }
}

extern "C" void kernel_launch(void* const* d_in, const int* in_sizes, int n_in,
                              void* d_out, int out_size) {
    const float* x     = (const float*)d_in[0];
    const float* wts   = (const float*)d_in[1];
    const float* W     = (const float*)d_in[2];
    const float* bias  = (const float*)d_in[3];
    const float* gamma = (const float*)d_in[4];
    const float* beta  = (const float*)d_in[5];
    float* out = (float*)d_out;

    int B = in_sizes[0] / 144;          // 262144
    int units = B / 256;                // 1024

    cudaFuncSetAttribute(k_persist, cudaFuncAttributeMaxDynamicSharedMemorySize, SMEM_BYTES);

    k_init<<<1, 32>>>();
    k_persist<<<GRID, BLK, SMEM_BYTES>>>(x, wts, W, bias, gamma, beta, out,
                                         units, 1.0f / (float)B);
}

// round 16
// speedup vs baseline: 1.4873x; 1.0443x over previous
#include <cuda_runtime.h>
#include <cstdint>

#define NQ   4
#define DIM  16
#define NC   4
#define BLK  256
#define WARPS_PER_BLK 8
#define GRID 148                                // 1 block/SM, all co-resident
#define WARPS_TOTAL (GRID * WARPS_PER_BLK)      // 1184
#define GROUP_ROWS 32
#define CHUNK_ROWS 16
#define ROW_PITCH 592                           // 576+16 pad: conflict-free LDS.128
#define CHUNK_BYTES (CHUNK_ROWS * ROW_PITCH)    // 9472
#define NBUF 3
#define WARP_SMEM (NBUF * CHUNK_BYTES)          // 28416
#define SMEM_BYTES (WARPS_PER_BLK * WARP_SMEM)  // 227328 (fits 227KB dynamic cap)
#define MAX_G 7                                 // ceil(8192 / 1184)

__device__ double g_part[GRID * 8];             // write-slots: no init needed
__device__ float  g_scale[NC];
__device__ float  g_shift[NC];
__device__ unsigned g_cnt;                      // monotonic across launches
__device__ volatile int g_flag;                 // generation flag, monotonic

__device__ __forceinline__ void cp16(char* dst_smem, const float4* src) {
    unsigned d = (unsigned)__cvta_generic_to_shared(dst_smem);
    asm volatile("cp.async.cg.shared.global [%0], [%1], 16;\n" :: "r"(d), "l"(src));
}
__device__ __forceinline__ void cp_commit() { asm volatile("cp.async.commit_group;\n"); }
template<int N> __device__ __forceinline__ void cp_wait() {
    asm volatile("cp.async.wait_group %0;\n" :: "n"(N));
}

// One 16-row chunk: 576 float4 coalesced, padded-pitch smem placement.
__device__ __forceinline__ void issue_chunk(char* wbuf, const float* x, size_t R, int lane) {
    const float4* src = (const float4*)(x + R * 144);
    #pragma unroll
    for (int k = 0; k < 18; k++) {
        const int r0  = (32 * k) / 36;
        const int rem = (32 * k) % 36;
        int ge  = (lane + rem) >= 36;
        int row = r0 + ge;
        int p   = lane + rem - (ge ? 36 : 0);
        cp16(wbuf + (uint32_t)row * ROW_PITCH + ((uint32_t)p << 4), src + lane + 32 * k);
    }
    cp_commit();
}

// Pool one chunk: lane l -> sample row (l&15), half (l>>4). Returns (left,right).
__device__ __forceinline__ void pool_chunk(const char* cbase, int lane, float& o0, float& o1) {
    int r = lane & 15, h = lane >> 4;
    const char* rb = cbase + (uint32_t)r * ROW_PITCH + (uint32_t)h * 288u;
    float a0 = 0.f, a1 = 0.f;
    #pragma unroll
    for (int j = 0; j < 18; j++) {
        float4 v = *(const float4*)(rb + 16 * j);
        if (j % 3 == 0)      { a0 += v.x + v.y + v.z + v.w; }
        else if (j % 3 == 1) { a0 += v.x + v.y; a1 += v.z + v.w; }
        else                 { a1 += v.x + v.y + v.z + v.w; }
    }
    o0 = a0; o1 = a1;
}

__global__ void __launch_bounds__(BLK, 1) k_persist(
    const float* __restrict__ x,
    const float* __restrict__ wts,
    const float* __restrict__ W,
    const float* __restrict__ bias,
    const float* __restrict__ gamma,
    const float* __restrict__ beta,
    float* __restrict__ out,
    int B, float invB)
{
    extern __shared__ char sbuf[];
    const int t = threadIdx.x;
    const int lane = t & 31;
    const int wid  = t >> 5;
    const int gw   = blockIdx.x * WARPS_PER_BLK + wid;
    char* wbuf = sbuf + wid * WARP_SMEM;

    const int totalGroups = B / GROUP_ROWS;              // 8192

    float wc[8], ws[8];
    #pragma unroll
    for (int i = 0; i < 8; i++) __sincosf(__ldg(&wts[i]) * 0.5f, &ws[i], &wc[i]);
    float Wr[16], bi[4];
    #pragma unroll
    for (int i = 0; i < 16; i++) Wr[i] = __ldg(&W[i]);
    #pragma unroll
    for (int i = 0; i < 4; i++)  bi[i] = __ldg(&bias[i]);

    float lg[MAX_G][4];
    float sum0=0.f,sum1=0.f,sum2=0.f,sum3=0.f, sq0=0.f,sq1=0.f,sq2=0.f,sq3=0.f;

    // prologue: chunks 0,1 (group 0) into bufs 0,1 -> 2 groups pending
    issue_chunk(wbuf + 0 * CHUNK_BYTES, x, (size_t)gw * GROUP_ROWS, lane);
    issue_chunk(wbuf + 1 * CHUNK_BYTES, x, (size_t)gw * GROUP_ROWS + CHUNK_ROWS, lane);

    #pragma unroll
    for (int kg = 0; kg < MAX_G; kg++) {
        int g = gw + kg * WARPS_TOTAL;
        if (g < totalGroups) {
            int gn = g + WARPS_TOTAL;
            bool hasnext = gn < totalGroups;
            size_t nrow = (size_t)gn * GROUP_ROWS;
            const int bE  = (2 * kg) % NBUF;         // even chunk buffer
            const int bO  = (2 * kg + 1) % NBUF;     // odd chunk buffer
            const int bNE = (2 * kg + 2) % NBUF;     // next even target
            const int bNO = (2 * kg + 3) % NBUF;     // next odd target (== bE)

            // pool even chunk (pending 2 -> wait<1> guarantees it)
            cp_wait<1>();
            __syncwarp();
            float uA0, uA1;
            pool_chunk(wbuf + bE * CHUNK_BYTES, lane, uA0, uA1);
            if (hasnext) issue_chunk(wbuf + bNE * CHUNK_BYTES, x, nrow, lane);

            // pool odd chunk
            if (hasnext) cp_wait<1>(); else cp_wait<0>();
            __syncwarp();
            float uB0, uB1;
            pool_chunk(wbuf + bO * CHUNK_BYTES, lane, uB0, uB1);
            __syncwarp();     // all lanes done reading bE before refilling it
            if (hasnext) issue_chunk(wbuf + bNO * CHUNK_BYTES, x, nrow + CHUNK_ROWS, lane);

            // merge: row r top half from lane r, bottom from lane r+16 (per chunk)
            int rl = lane & 15;
            float a0 = __shfl_sync(0xFFFFFFFFu, uA0, rl);
            float a1 = __shfl_sync(0xFFFFFFFFu, uA1, rl);
            float a2 = __shfl_sync(0xFFFFFFFFu, uA0, rl + 16);
            float a3 = __shfl_sync(0xFFFFFFFFu, uA1, rl + 16);
            float b0 = __shfl_sync(0xFFFFFFFFu, uB0, rl);
            float b1 = __shfl_sync(0xFFFFFFFFu, uB1, rl);
            float b2 = __shfl_sync(0xFFFFFFFFu, uB0, rl + 16);
            float b3 = __shfl_sync(0xFFFFFFFFu, uB1, rl + 16);
            bool lo = lane < 16;
            float s0 = lo ? a0 : b0;   // top-left
            float s1 = lo ? a1 : b1;   // top-right
            float s2 = lo ? a2 : b2;   // bottom-left
            float s3 = lo ? a3 : b3;   // bottom-right

            // ---- circuit (fused RX+RY1 product state; final CZ dropped) ----
            const float inv72 = 1.f / 72.f;
            float cp4[4], sp4[4];
            __sincosf(s0 * inv72, &sp4[0], &cp4[0]);
            __sincosf(s1 * inv72, &sp4[1], &cp4[1]);
            __sincosf(s2 * inv72, &sp4[2], &cp4[2]);
            __sincosf(s3 * inv72, &sp4[3], &cp4[3]);

            float v0r[4], v0i[4], v1r[4], v1i[4];
            #pragma unroll
            for (int i = 0; i < 4; i++) {
                float cw = wc[i], sw = ws[i];
                v0r[i] =  cw * cp4[i];  v0i[i] =  sw * sp4[i];
                v1r[i] =  sw * cp4[i];  v1i[i] = -cw * sp4[i];
            }
            float p01r[4], p01i[4], p23r[4], p23i[4];
            #pragma unroll
            for (int a = 0; a < 2; a++) {
                float ar0 = a ? v1r[0] : v0r[0], ai0 = a ? v1i[0] : v0i[0];
                float ar2 = a ? v1r[2] : v0r[2], ai2 = a ? v1i[2] : v0i[2];
                #pragma unroll
                for (int c = 0; c < 2; c++) {
                    float br1 = c ? v1r[1] : v0r[1], bi1 = c ? v1i[1] : v0i[1];
                    float br3 = c ? v1r[3] : v0r[3], bi3 = c ? v1i[3] : v0i[3];
                    p01r[a*2+c] = ar0 * br1 - ai0 * bi1;
                    p01i[a*2+c] = ar0 * bi1 + ai0 * br1;
                    p23r[a*2+c] = ar2 * br3 - ai2 * bi3;
                    p23i[a*2+c] = ar2 * bi3 + ai2 * br3;
                }
            }
            float re[DIM], im[DIM];
            #pragma unroll
            for (int k = 0; k < DIM; k++) {
                int a = (k >> 2) & 3, c = k & 3;
                float rr = p01r[a] * p23r[c] - p01i[a] * p23i[c];
                float ii = p01r[a] * p23i[c] + p01i[a] * p23r[c];
                int par = (((k >> 3) & (k >> 2)) ^ ((k >> 2) & (k >> 1)) ^ ((k >> 1) & k)) & 1;
                re[k] = par ? -rr : rr;
                im[k] = par ? -ii : ii;
            }
            #pragma unroll
            for (int w = 0; w < NQ; w++) {
                float cc = wc[4 + w], ss = ws[4 + w];
                int bit = 1 << (3 - w);
                #pragma unroll
                for (int k = 0; k < DIM; k++) {
                    if (!(k & bit)) {
                        int k1 = k | bit;
                        float r0 = re[k], r1 = re[k1];
                        re[k]  = cc * r0 - ss * r1;
                        re[k1] = ss * r0 + cc * r1;
                        float i0 = im[k], i1 = im[k1];
                        im[k]  = cc * i0 - ss * i1;
                        im[k1] = ss * i0 + cc * i1;
                    }
                }
            }
            float q0=0.f, q1=0.f, q2=0.f, q3=0.f;
            #pragma unroll
            for (int k = 0; k < DIM; k++) {
                float p = re[k] * re[k] + im[k] * im[k];
                q0 += (k & 8) ? -p : p;
                q1 += (k & 4) ? -p : p;
                q2 += (k & 2) ? -p : p;
                q3 += (k & 1) ? -p : p;
            }
            #pragma unroll
            for (int c2 = 0; c2 < NC; c2++) {
                lg[kg][c2] = bi[c2] + q0 * Wr[c2*4+0] + q1 * Wr[c2*4+1]
                                    + q2 * Wr[c2*4+2] + q3 * Wr[c2*4+3];
            }
            sum0 += lg[kg][0]; sum1 += lg[kg][1]; sum2 += lg[kg][2]; sum3 += lg[kg][3];
            sq0 += lg[kg][0]*lg[kg][0]; sq1 += lg[kg][1]*lg[kg][1];
            sq2 += lg[kg][2]*lg[kg][2]; sq3 += lg[kg][3]*lg[kg][3];
        }
    }

    // ---- block reduction (reuse smem: rsm float[64] @0, dsm double[8] @256, ctrl int[2] @320)
    float* rsm  = (float*)sbuf;
    double* dsm = (double*)(sbuf + 256);
    int* ctrl   = (int*)(sbuf + 320);

    float red[8] = {sum0,sum1,sum2,sum3,sq0,sq1,sq2,sq3};
    #pragma unroll
    for (int off = 16; off > 0; off >>= 1) {
        #pragma unroll
        for (int j = 0; j < 8; j++)
            red[j] += __shfl_down_sync(0xFFFFFFFFu, red[j], off);
    }
    __syncthreads();                    // pipeline smem reads all done
    if (lane == 0) {
        #pragma unroll
        for (int j = 0; j < 8; j++) rsm[j * 8 + wid] = red[j];
    }
    __syncthreads();
    if (t < 8) {
        float acc = 0.f;
        #pragma unroll
        for (int wgi = 0; wgi < 8; wgi++) acc += rsm[t * 8 + wgi];
        g_part[blockIdx.x * 8 + t] = (double)acc;
        __threadfence();
    }
    __syncthreads();

    // ---- generation grid barrier (148 blocks, 1/SM; counters monotonic, no init kernel)
    if (t == 0) {
        unsigned r = atomicAdd(&g_cnt, 1u);
        ctrl[0] = (r % GRID == GRID - 1u) ? 1 : 0;
        ctrl[1] = (int)(r / GRID);                 // generation
        __threadfence();
    }
    __syncthreads();
    int isLast = ctrl[0], gen = ctrl[1];

    if (isLast) {
        if (t < 64) {
            int c = t >> 3, j = t & 7;
            double acc = 0.0;
            for (int bb = j; bb < GRID; bb += 8) acc += g_part[bb * 8 + c];
            acc += __shfl_xor_sync(0xFFFFFFFFu, acc, 1);
            acc += __shfl_xor_sync(0xFFFFFFFFu, acc, 2);
            acc += __shfl_xor_sync(0xFFFFFFFFu, acc, 4);
            if (j == 0) dsm[c] = acc;
        }
        __syncthreads();
        if (t < 4) {
            double m = dsm[t] * (double)invB;
            double v = dsm[4 + t] * (double)invB - m * m;
            float inv = rsqrtf((float)v + 1e-5f);
            g_scale[t] = __ldg(&gamma[t]) * inv;
            g_shift[t] = __ldg(&beta[t]) - (float)m * inv * __ldg(&gamma[t]);
        }
        __threadfence();
        __syncthreads();
        if (t == 0) atomicExch((int*)&g_flag, gen + 1);
    } else {
        if (t == 0) {
            while (g_flag < gen + 1) __nanosleep(64);
        }
    }
    __syncthreads();

    float sc[4], sh[4];
    #pragma unroll
    for (int c2 = 0; c2 < NC; c2++) {
        sc[c2] = *((volatile float*)&g_scale[c2]);
        sh[c2] = *((volatile float*)&g_shift[c2]);
    }

    // ---- coalesced normalized write ----
    float4* o4 = (float4*)out;
    #pragma unroll
    for (int kg = 0; kg < MAX_G; kg++) {
        int g = gw + kg * WARPS_TOTAL;
        if (g < totalGroups) {
            o4[(size_t)g * GROUP_ROWS + lane] =
                make_float4(lg[kg][0]*sc[0]+sh[0], lg[kg][1]*sc[1]+sh[1],
                            lg[kg][2]*sc[2]+sh[2], lg[kg][3]*sc[3]+sh[3]);
        }
    }
}

extern "C" void kernel_launch(void* const* d_in, const int* in_sizes, int n_in,
                              void* d_out, int out_size) {
    const float* x     = (const float*)d_in[0];
    const float* wts   = (const float*)d_in[1];
    const float* W     = (const float*)d_in[2];
    const float* bias  = (const float*)d_in[3];
    const float* gamma = (const float*)d_in[4];
    const float* beta  = (const float*)d_in[5];
    float* out = (float*)d_out;

    int B = in_sizes[0] / 144;    // 262144

    cudaFuncSetAttribute(k_persist, cudaFuncAttributeMaxDynamicSharedMemorySize, SMEM_BYTES);

    k_persist<<<GRID, BLK, SMEM_BYTES>>>(x, wts, W, bias, gamma, beta, out,
                                         B, 1.0f / (float)B);
}